// round 2
// baseline (speedup 1.0000x reference)
#include <cuda_runtime.h>
#include <math.h>

#define BATCH 16
#define LQ 128
#define LP 512
#define H 32
#define DH 32
#define INNERD 1024
#define DIMD 256
#define SST 68                     /* padded row stride for s tile */
#define SCALE 0.17677669529663687f /* 32^-0.5 */

// ---------------- scratch (static device arrays; no allocs) ----------------
__device__ float g_QK[2048 * 1024];          // [n][h*32+d]
__device__ float g_CQKt[16 * 1024 * 512];    // [b][c=h*32+d][j]  (transposed)
__device__ float g_CV[8192 * 1024];          // [b*512+j][h*32+d]

__device__ __forceinline__ float mishf(float x) {
    float sp = (x > 20.f) ? x : log1pf(__expf(x));
    return x * tanhf(sp);
}

// ---------------- projection GEMM: out = A[M,256] @ W[256,1024] -----------
// mode 0 -> g_QK (plain), 1 -> g_CQKt (transposed per batch of 512 rows), 2 -> g_CV (plain)
__global__ __launch_bounds__(256) void proj_gemm(const float* __restrict__ A,
                                                 const float* __restrict__ W,
                                                 int M, int mode) {
    __shared__ float sAT[32][68];
    __shared__ float sB[32][68];
    __shared__ float sC[64][68];

    float* outp = (mode == 0) ? g_QK : (mode == 1 ? g_CQKt : g_CV);

    int t = threadIdx.x;
    int m0 = blockIdx.x * 64;
    int n0 = blockIdx.y * 64;
    int ty = t >> 4, tx = t & 15;

    float acc[4][4];
#pragma unroll
    for (int a = 0; a < 4; a++)
#pragma unroll
        for (int bq = 0; bq < 4; bq++) acc[a][bq] = 0.f;

    for (int k0 = 0; k0 < 256; k0 += 32) {
        // load A tile (64 x 32) transposed into sAT[kk][r]
#pragma unroll
        for (int f = 0; f < 2; f++) {
            int qid = t + 256 * f;          // 0..511
            int r = qid >> 3, kq = qid & 7; // r 0..63, kq 0..7
            float4 v = reinterpret_cast<const float4*>(A)[(size_t)(m0 + r) * 64 + (k0 >> 2) + kq];
            sAT[kq * 4 + 0][r] = v.x;
            sAT[kq * 4 + 1][r] = v.y;
            sAT[kq * 4 + 2][r] = v.z;
            sAT[kq * 4 + 3][r] = v.w;
        }
        // load W tile (32 x 64)
#pragma unroll
        for (int f = 0; f < 2; f++) {
            int qid = t + 256 * f;
            int kk = qid >> 4, cq = qid & 15;
            *reinterpret_cast<float4*>(&sB[kk][cq * 4]) =
                reinterpret_cast<const float4*>(W)[(size_t)(k0 + kk) * 256 + (n0 >> 2) + cq];
        }
        __syncthreads();
#pragma unroll
        for (int kk = 0; kk < 32; kk++) {
            float4 a4 = *reinterpret_cast<const float4*>(&sAT[kk][ty * 4]);
            float4 b4 = *reinterpret_cast<const float4*>(&sB[kk][tx * 4]);
            float av[4] = {a4.x, a4.y, a4.z, a4.w};
            float bv[4] = {b4.x, b4.y, b4.z, b4.w};
#pragma unroll
            for (int a = 0; a < 4; a++)
#pragma unroll
                for (int bq = 0; bq < 4; bq++) acc[a][bq] += av[a] * bv[bq];
        }
        __syncthreads();
    }

    if (mode != 1) {
#pragma unroll
        for (int a = 0; a < 4; a++) {
            float4 v = make_float4(acc[a][0], acc[a][1], acc[a][2], acc[a][3]);
            *reinterpret_cast<float4*>(&outp[(size_t)(m0 + ty * 4 + a) * 1024 + n0 + tx * 4]) = v;
        }
    } else {
        // stage to smem, then write transposed coalesced over j
#pragma unroll
        for (int a = 0; a < 4; a++) {
            float4 v = make_float4(acc[a][0], acc[a][1], acc[a][2], acc[a][3]);
            *reinterpret_cast<float4*>(&sC[ty * 4 + a][tx * 4]) = v;
        }
        __syncthreads();
        int bb = m0 >> 9;
        int jbase = m0 & 511;
#pragma unroll
        for (int f = 0; f < 16; f++) {
            int idx = t + 256 * f; // 0..4095
            int cc = idx >> 6, jj = idx & 63;
            outp[((size_t)bb * 1024 + n0 + cc) * 512 + jbase + jj] = sC[jj][cc];
        }
    }
}

// ---------------- fused attention kernel: one CTA per (b, i) --------------
// smem layout (floats):
#define OFF_S 0
#define OFF_QK 34816
#define OFF_H 35840
#define OFF_P 36352
#define OFF_RED 37376
#define OFF_MAX 37632
#define OFF_INV 37696
#define OFF_O 37760
#define OFF_PO 38784
#define OFF_DIS 39808
#define OFF_OD 41344
#define OFF_HD 41440
#define SMEM_FLOATS 41632
#define SMEM_BYTES (SMEM_FLOATS * 4)

__global__ __launch_bounds__(256, 1) void fused_attn(
    const float* __restrict__ dis, const float* __restrict__ dis_emb,
    const float* __restrict__ W_m1, const float* __restrict__ W_m2,
    const float* __restrict__ b_m2, const float* __restrict__ W_o,
    const float* __restrict__ b_o, const float* __restrict__ W_d1,
    const float* __restrict__ b_d1, const float* __restrict__ W_d2,
    const float* __restrict__ b_d2, float* __restrict__ out) {
    extern __shared__ float sm[];
    float* sS = sm + OFF_S;
    float* sQK = sm + OFF_QK;
    float* sH = sm + OFF_H;
    float* sP = sm + OFF_P;
    float* sRed = sm + OFF_RED;
    float* sMax = sm + OFF_MAX;
    float* sInv = sm + OFF_INV;
    float* sO = sm + OFF_O;
    float* sPo = sm + OFF_PO;
    float* sDis = sm + OFF_DIS;
    float* sOd = sm + OFF_OD;
    float* sHd = sm + OFF_HD;

    int t = threadIdx.x;
    int n = blockIdx.x;
    int b = n >> 7, i = n & 127;

    // ---- phase 0: load qk row + dis_emb channels ----
    reinterpret_cast<float4*>(sQK)[t] =
        reinterpret_cast<const float4*>(g_QK)[(size_t)n * 256 + t];
    const float* de = dis_emb + ((size_t)b * LP * LQ + i) * H;
    for (int idx = t; idx < LP * H; idx += 256) {
        int j = idx >> 5, h = idx & 31;
        sS[j * SST + 32 + h] = de[(size_t)j * LQ * H + h];
    }
    __syncthreads();

    // ---- phase 1: sim (coalesced over j via transposed CQK) ----
    {
        int jq = t & 127;       // j quad
        int h0 = (t >> 7) * 16; // 16 heads per half
        const float4* cq = reinterpret_cast<const float4*>(g_CQKt);
        for (int hh = 0; hh < 16; hh++) {
            int h = h0 + hh;
            const float* qrow = sQK + h * 32;
            size_t base = ((size_t)b * 1024 + h * 32) * 128 + jq;
            float4 acc = make_float4(0.f, 0.f, 0.f, 0.f);
#pragma unroll
            for (int d = 0; d < 32; d++) {
                float q = qrow[d];
                float4 c4 = cq[base + (size_t)d * 128];
                acc.x += q * c4.x;
                acc.y += q * c4.y;
                acc.z += q * c4.z;
                acc.w += q * c4.w;
            }
            int j0 = jq * 4;
            sS[(j0 + 0) * SST + h] = acc.x * SCALE;
            sS[(j0 + 1) * SST + h] = acc.y * SCALE;
            sS[(j0 + 2) * SST + h] = acc.z * SCALE;
            sS[(j0 + 3) * SST + h] = acc.w * SCALE;
        }
    }
    __syncthreads();

    // ---- phase 2: attention MLP (weights in registers) ----
    float w1[64], w2[32];
    {
        int u = t & 127;
#pragma unroll
        for (int k = 0; k < 64; k++) w1[k] = W_m1[k * 128 + u];
        int c = t & 63, ch = t >> 6;
#pragma unroll
        for (int k = 0; k < 32; k++) w2[k] = W_m2[(ch * 32 + k) * 64 + c];
    }
    float bm2 = b_m2[t & 63];

    for (int r = 0; r < 128; r++) {
        int j0 = r * 4;
        // A: hidden = mish(s @ W1)
        {
            int u = t & 127;
            int jj0 = t >> 7;
#pragma unroll
            for (int s2 = 0; s2 < 2; s2++) {
                int jj = jj0 + 2 * s2;
                const float4* srow = reinterpret_cast<const float4*>(sS + (j0 + jj) * SST);
                float acc = 0.f;
#pragma unroll
                for (int k4 = 0; k4 < 16; k4++) {
                    float4 sv = srow[k4];
                    acc += sv.x * w1[k4 * 4 + 0] + sv.y * w1[k4 * 4 + 1] +
                           sv.z * w1[k4 * 4 + 2] + sv.w * w1[k4 * 4 + 3];
                }
                sH[jj * 128 + u] = mishf(acc);
            }
        }
        __syncthreads();
        // B: partial out = hidden @ W2 (k split over 4 chunks)
        {
            int c = t & 63, ch = t >> 6;
#pragma unroll
            for (int jj = 0; jj < 4; jj++) {
                const float4* hrow =
                    reinterpret_cast<const float4*>(sH + jj * 128 + ch * 32);
                float p = 0.f;
#pragma unroll
                for (int k4 = 0; k4 < 8; k4++) {
                    float4 hv = hrow[k4];
                    p += hv.x * w2[k4 * 4 + 0] + hv.y * w2[k4 * 4 + 1] +
                         hv.z * w2[k4 * 4 + 2] + hv.w * w2[k4 * 4 + 3];
                }
                sP[jj * 256 + ch * 64 + c] = p;
            }
        }
        __syncthreads();
        // C: reduce partials + bias -> back into sS
        {
            int jj = t >> 6, c2 = t & 63;
            float v = sP[jj * 256 + c2] + sP[jj * 256 + 64 + c2] +
                      sP[jj * 256 + 128 + c2] + sP[jj * 256 + 192 + c2] + bm2;
            sS[(j0 + jj) * SST + c2] = v;
        }
        __syncthreads();
    }

    // ---- phase 3: softmax over j, per channel ----
    {
        int c = t & 63, q = t >> 6;
        int jb = q * 128;
        float m = -1e30f;
        for (int j = jb; j < jb + 128; j++) m = fmaxf(m, sS[j * SST + c]);
        sRed[q * 64 + c] = m;
        __syncthreads();
        if (t < 64) {
            sMax[t] = fmaxf(fmaxf(sRed[t], sRed[64 + t]),
                            fmaxf(sRed[128 + t], sRed[192 + t]));
        }
        __syncthreads();
        float mx = sMax[c];
        float ssum = 0.f;
        for (int j = jb; j < jb + 128; j++) {
            float e = __expf(sS[j * SST + c] - mx);
            sS[j * SST + c] = e;
            ssum += e;
        }
        sRed[q * 64 + c] = ssum;
        __syncthreads();
        if (t < 64)
            sInv[t] = 1.f / (sRed[t] + sRed[64 + t] + sRed[128 + t] + sRed[192 + t]);
        __syncthreads();
    }

    // ---- phase 4a: out = (attn[:, :32] @ CV) @ W_o + b_o ----
    {
        int h = t >> 3, dq = t & 7;
        const float4* cv4 = reinterpret_cast<const float4*>(g_CV);
        size_t base = (size_t)b * 131072 + h * 8 + dq;
        float4 acc = make_float4(0.f, 0.f, 0.f, 0.f);
#pragma unroll 4
        for (int j = 0; j < 512; j++) {
            float a = sS[j * SST + h];
            float4 v = cv4[base + (size_t)j * 256];
            acc.x += a * v.x;
            acc.y += a * v.y;
            acc.z += a * v.z;
            acc.w += a * v.w;
        }
        float inv = sInv[h];
        reinterpret_cast<float4*>(sO)[h * 8 + dq] =
            make_float4(acc.x * inv, acc.y * inv, acc.z * inv, acc.w * inv);
    }
    __syncthreads();
    {
        int cq = t & 63, kk = t >> 6;
        const float4* wo4 = reinterpret_cast<const float4*>(W_o);
        float4 acc = make_float4(0.f, 0.f, 0.f, 0.f);
        int kend = kk * 256 + 256;
#pragma unroll 4
        for (int k = kk * 256; k < kend; k++) {
            float s = sO[k];
            float4 w = wo4[(size_t)k * 64 + cq];
            acc.x += s * w.x;
            acc.y += s * w.y;
            acc.z += s * w.z;
            acc.w += s * w.w;
        }
        reinterpret_cast<float4*>(sPo)[kk * 64 + cq] = acc;
    }
    __syncthreads();
    {
        float v = sPo[t] + sPo[256 + t] + sPo[512 + t] + sPo[768 + t] + b_o[t];
        out[(size_t)n * 256 + t] = v;
    }

    // ---- phase 4b: out_dis ----
    {
        const float* dd = dis + ((size_t)b * LP * LQ + i) * 3;
        for (int idx = t; idx < 1536; idx += 256) {
            int j = idx / 3, d = idx - 3 * j;
            sDis[idx] = dd[(size_t)j * LQ * 3 + d];
        }
    }
    __syncthreads();
    if (t < 96) {
        int h = t & 31, d = t >> 5;
        float acc = 0.f;
#pragma unroll 4
        for (int j = 0; j < 512; j++) acc += sS[j * SST + 32 + h] * sDis[j * 3 + d];
        sOd[d * 32 + h] = acc * sInv[32 + h];
    }
    __syncthreads();
    if (t < 192) {
        int r3 = t >> 6, u = t & 63;
        float acc = b_d1[u];
#pragma unroll
        for (int k = 0; k < 32; k++) acc += sOd[r3 * 32 + k] * W_d1[k * 64 + u];
        sHd[r3 * 64 + u] = mishf(acc);
    }
    __syncthreads();
    if (t < 96) {
        int h = t & 31, d = t >> 5;
        float acc = b_d2[h];
#pragma unroll
        for (int k = 0; k < 64; k++) acc += sHd[d * 64 + k] * W_d2[k * 32 + h];
        out[524288 + ((size_t)n * 3 + d) * 32 + h] = acc;
    }
}

// ---------------- launch ----------------
extern "C" void kernel_launch(void* const* d_in, const int* in_sizes, int n_in,
                              void* d_out, int out_size) {
    const float* x = (const float*)d_in[0];
    const float* context = (const float*)d_in[1];
    const float* dis = (const float*)d_in[2];
    const float* dis_emb = (const float*)d_in[3];
    // scalars protein_len / ligand_len may or may not be materialized as inputs
    int wb = (n_in == 17) ? 4 : 6;
    const float* W_qk = (const float*)d_in[wb + 0];
    const float* W_cqk = (const float*)d_in[wb + 2];
    const float* W_cv = (const float*)d_in[wb + 3];
    const float* W_m1 = (const float*)d_in[wb + 4];
    const float* W_m2 = (const float*)d_in[wb + 5];
    const float* b_m2 = (const float*)d_in[wb + 6];
    const float* W_o = (const float*)d_in[wb + 7];
    const float* b_o = (const float*)d_in[wb + 8];
    const float* W_d1 = (const float*)d_in[wb + 9];
    const float* b_d1 = (const float*)d_in[wb + 10];
    const float* W_d2 = (const float*)d_in[wb + 11];
    const float* b_d2 = (const float*)d_in[wb + 12];
    float* out = (float*)d_out;

    // projections
    proj_gemm<<<dim3(32, 16), 256>>>(x, W_qk, 2048, 0);        // QK
    proj_gemm<<<dim3(128, 16), 256>>>(context, W_cqk, 8192, 1); // CQK (transposed)
    proj_gemm<<<dim3(128, 16), 256>>>(context, W_cv, 8192, 2);  // CV

    static int smem_set = 0;
    (void)smem_set;
    cudaFuncSetAttribute(fused_attn, cudaFuncAttributeMaxDynamicSharedMemorySize,
                         SMEM_BYTES);
    fused_attn<<<2048, 256, SMEM_BYTES>>>(dis, dis_emb, W_m1, W_m2, b_m2, W_o,
                                          b_o, W_d1, b_d1, W_d2, b_d2, out);
}

// round 3
// speedup vs baseline: 1.0024x; 1.0024x over previous
#include <cuda_runtime.h>
#include <math.h>

#define BATCH 16
#define LQ 128
#define LP 512
#define H 32
#define DH 32
#define INNERD 1024
#define DIMD 256
#define SST 68                     /* padded row stride for s tile */
#define SCALE 0.17677669529663687f /* 32^-0.5 */

// ---------------- scratch (static device arrays; no allocs) ----------------
__device__ float g_QK[2048 * 1024];          // [n][h*32+d]
__device__ float g_CQKt[16 * 1024 * 512];    // [b][c=h*32+d][j]  (transposed)
__device__ float g_CV[8192 * 1024];          // [b*512+j][h*32+d]

__device__ __forceinline__ float mishf(float x) {
    float sp = (x > 20.f) ? x : log1pf(__expf(x));
    return x * tanhf(sp);
}

// ---------------- projection GEMM: out = A[M,256] @ W[256,1024] -----------
// mode 0 -> g_QK (plain), 1 -> g_CQKt (transposed per batch of 512 rows), 2 -> g_CV (plain)
__global__ __launch_bounds__(256) void proj_gemm(const float* __restrict__ A,
                                                 const float* __restrict__ W,
                                                 int M, int mode) {
    __shared__ float sAT[32][68];
    __shared__ float sB[32][68];
    __shared__ float sC[64][68];

    float* outp = (mode == 0) ? g_QK : (mode == 1 ? g_CQKt : g_CV);

    int t = threadIdx.x;
    int m0 = blockIdx.x * 64;
    int n0 = blockIdx.y * 64;
    int ty = t >> 4, tx = t & 15;

    float acc[4][4];
#pragma unroll
    for (int a = 0; a < 4; a++)
#pragma unroll
        for (int bq = 0; bq < 4; bq++) acc[a][bq] = 0.f;

    for (int k0 = 0; k0 < 256; k0 += 32) {
        // load A tile (64 x 32) transposed into sAT[kk][r]
#pragma unroll
        for (int f = 0; f < 2; f++) {
            int qid = t + 256 * f;          // 0..511
            int r = qid >> 3, kq = qid & 7; // r 0..63, kq 0..7
            float4 v = reinterpret_cast<const float4*>(A)[(size_t)(m0 + r) * 64 + (k0 >> 2) + kq];
            sAT[kq * 4 + 0][r] = v.x;
            sAT[kq * 4 + 1][r] = v.y;
            sAT[kq * 4 + 2][r] = v.z;
            sAT[kq * 4 + 3][r] = v.w;
        }
        // load W tile (32 x 64)
#pragma unroll
        for (int f = 0; f < 2; f++) {
            int qid = t + 256 * f;
            int kk = qid >> 4, cq = qid & 15;
            *reinterpret_cast<float4*>(&sB[kk][cq * 4]) =
                reinterpret_cast<const float4*>(W)[(size_t)(k0 + kk) * 256 + (n0 >> 2) + cq];
        }
        __syncthreads();
#pragma unroll
        for (int kk = 0; kk < 32; kk++) {
            float4 a4 = *reinterpret_cast<const float4*>(&sAT[kk][ty * 4]);
            float4 b4 = *reinterpret_cast<const float4*>(&sB[kk][tx * 4]);
            float av[4] = {a4.x, a4.y, a4.z, a4.w};
            float bv[4] = {b4.x, b4.y, b4.z, b4.w};
#pragma unroll
            for (int a = 0; a < 4; a++)
#pragma unroll
                for (int bq = 0; bq < 4; bq++) acc[a][bq] += av[a] * bv[bq];
        }
        __syncthreads();
    }

    if (mode != 1) {
#pragma unroll
        for (int a = 0; a < 4; a++) {
            float4 v = make_float4(acc[a][0], acc[a][1], acc[a][2], acc[a][3]);
            *reinterpret_cast<float4*>(&outp[(size_t)(m0 + ty * 4 + a) * 1024 + n0 + tx * 4]) = v;
        }
    } else {
        // stage to smem, then write transposed coalesced over j
#pragma unroll
        for (int a = 0; a < 4; a++) {
            float4 v = make_float4(acc[a][0], acc[a][1], acc[a][2], acc[a][3]);
            *reinterpret_cast<float4*>(&sC[ty * 4 + a][tx * 4]) = v;
        }
        __syncthreads();
        int bb = m0 >> 9;
        int jbase = m0 & 511;
#pragma unroll
        for (int f = 0; f < 16; f++) {
            int idx = t + 256 * f; // 0..4095
            int cc = idx >> 6, jj = idx & 63;
            outp[((size_t)bb * 1024 + n0 + cc) * 512 + jbase + jj] = sC[jj][cc];
        }
    }
}

// ---------------- fused attention kernel: one CTA per (b, i) --------------
// smem layout (floats):
#define OFF_S 0
#define OFF_QK 34816
#define OFF_H 35840
#define OFF_P 36352
#define OFF_RED 37376
#define OFF_MAX 37632
#define OFF_INV 37696
#define OFF_O 37760
#define OFF_PO 38784
#define OFF_DIS 39808
#define OFF_OD 41344
#define OFF_HD 41440
#define SMEM_FLOATS 41632
#define SMEM_BYTES (SMEM_FLOATS * 4)

__global__ __launch_bounds__(256, 1) void fused_attn(
    const float* __restrict__ dis, const float* __restrict__ dis_emb,
    const float* __restrict__ W_m1, const float* __restrict__ W_m2,
    const float* __restrict__ b_m2, const float* __restrict__ W_o,
    const float* __restrict__ b_o, const float* __restrict__ W_d1,
    const float* __restrict__ b_d1, const float* __restrict__ W_d2,
    const float* __restrict__ b_d2, float* __restrict__ out) {
    extern __shared__ float sm[];
    float* sS = sm + OFF_S;
    float* sQK = sm + OFF_QK;
    float* sH = sm + OFF_H;
    float* sP = sm + OFF_P;
    float* sRed = sm + OFF_RED;
    float* sMax = sm + OFF_MAX;
    float* sInv = sm + OFF_INV;
    float* sO = sm + OFF_O;
    float* sPo = sm + OFF_PO;
    float* sDis = sm + OFF_DIS;
    float* sOd = sm + OFF_OD;
    float* sHd = sm + OFF_HD;

    int t = threadIdx.x;
    int n = blockIdx.x;
    int b = n >> 7, i = n & 127;

    // ---- phase 0: load qk row + dis_emb channels ----
    reinterpret_cast<float4*>(sQK)[t] =
        reinterpret_cast<const float4*>(g_QK)[(size_t)n * 256 + t];
    const float* de = dis_emb + ((size_t)b * LP * LQ + i) * H;
    for (int idx = t; idx < LP * H; idx += 256) {
        int j = idx >> 5, h = idx & 31;
        sS[j * SST + 32 + h] = de[(size_t)j * LQ * H + h];
    }
    __syncthreads();

    // ---- phase 1: sim (coalesced over j via transposed CQK) ----
    {
        int jq = t & 127;       // j quad
        int h0 = (t >> 7) * 16; // 16 heads per half
        const float4* cq = reinterpret_cast<const float4*>(g_CQKt);
        for (int hh = 0; hh < 16; hh++) {
            int h = h0 + hh;
            const float* qrow = sQK + h * 32;
            size_t base = ((size_t)b * 1024 + h * 32) * 128 + jq;
            float4 acc = make_float4(0.f, 0.f, 0.f, 0.f);
#pragma unroll
            for (int d = 0; d < 32; d++) {
                float q = qrow[d];
                float4 c4 = cq[base + (size_t)d * 128];
                acc.x += q * c4.x;
                acc.y += q * c4.y;
                acc.z += q * c4.z;
                acc.w += q * c4.w;
            }
            int j0 = jq * 4;
            sS[(j0 + 0) * SST + h] = acc.x * SCALE;
            sS[(j0 + 1) * SST + h] = acc.y * SCALE;
            sS[(j0 + 2) * SST + h] = acc.z * SCALE;
            sS[(j0 + 3) * SST + h] = acc.w * SCALE;
        }
    }
    __syncthreads();

    // ---- phase 2: attention MLP (weights in registers) ----
    float w1[64], w2[32];
    {
        int u = t & 127;
#pragma unroll
        for (int k = 0; k < 64; k++) w1[k] = W_m1[k * 128 + u];
        int c = t & 63, ch = t >> 6;
#pragma unroll
        for (int k = 0; k < 32; k++) w2[k] = W_m2[(ch * 32 + k) * 64 + c];
    }
    float bm2 = b_m2[t & 63];

    for (int r = 0; r < 128; r++) {
        int j0 = r * 4;
        // A: hidden = mish(s @ W1)
        {
            int u = t & 127;
            int jj0 = t >> 7;
#pragma unroll
            for (int s2 = 0; s2 < 2; s2++) {
                int jj = jj0 + 2 * s2;
                const float4* srow = reinterpret_cast<const float4*>(sS + (j0 + jj) * SST);
                float acc = 0.f;
#pragma unroll
                for (int k4 = 0; k4 < 16; k4++) {
                    float4 sv = srow[k4];
                    acc += sv.x * w1[k4 * 4 + 0] + sv.y * w1[k4 * 4 + 1] +
                           sv.z * w1[k4 * 4 + 2] + sv.w * w1[k4 * 4 + 3];
                }
                sH[jj * 128 + u] = mishf(acc);
            }
        }
        __syncthreads();
        // B: partial out = hidden @ W2 (k split over 4 chunks)
        {
            int c = t & 63, ch = t >> 6;
#pragma unroll
            for (int jj = 0; jj < 4; jj++) {
                const float4* hrow =
                    reinterpret_cast<const float4*>(sH + jj * 128 + ch * 32);
                float p = 0.f;
#pragma unroll
                for (int k4 = 0; k4 < 8; k4++) {
                    float4 hv = hrow[k4];
                    p += hv.x * w2[k4 * 4 + 0] + hv.y * w2[k4 * 4 + 1] +
                         hv.z * w2[k4 * 4 + 2] + hv.w * w2[k4 * 4 + 3];
                }
                sP[jj * 256 + ch * 64 + c] = p;
            }
        }
        __syncthreads();
        // C: reduce partials + bias -> back into sS
        {
            int jj = t >> 6, c2 = t & 63;
            float v = sP[jj * 256 + c2] + sP[jj * 256 + 64 + c2] +
                      sP[jj * 256 + 128 + c2] + sP[jj * 256 + 192 + c2] + bm2;
            sS[(j0 + jj) * SST + c2] = v;
        }
        __syncthreads();
    }

    // ---- phase 3: softmax over j, per channel ----
    {
        int c = t & 63, q = t >> 6;
        int jb = q * 128;
        float m = -1e30f;
        for (int j = jb; j < jb + 128; j++) m = fmaxf(m, sS[j * SST + c]);
        sRed[q * 64 + c] = m;
        __syncthreads();
        if (t < 64) {
            sMax[t] = fmaxf(fmaxf(sRed[t], sRed[64 + t]),
                            fmaxf(sRed[128 + t], sRed[192 + t]));
        }
        __syncthreads();
        float mx = sMax[c];
        float ssum = 0.f;
        for (int j = jb; j < jb + 128; j++) {
            float e = __expf(sS[j * SST + c] - mx);
            sS[j * SST + c] = e;
            ssum += e;
        }
        sRed[q * 64 + c] = ssum;
        __syncthreads();
        if (t < 64)
            sInv[t] = 1.f / (sRed[t] + sRed[64 + t] + sRed[128 + t] + sRed[192 + t]);
        __syncthreads();
    }

    // ---- phase 4a: out = (attn[:, :32] @ CV) @ W_o + b_o ----
    {
        int h = t >> 3, dq = t & 7;
        const float4* cv4 = reinterpret_cast<const float4*>(g_CV);
        size_t base = (size_t)b * 131072 + h * 8 + dq;
        float4 acc = make_float4(0.f, 0.f, 0.f, 0.f);
#pragma unroll 4
        for (int j = 0; j < 512; j++) {
            float a = sS[j * SST + h];
            float4 v = cv4[base + (size_t)j * 256];
            acc.x += a * v.x;
            acc.y += a * v.y;
            acc.z += a * v.z;
            acc.w += a * v.w;
        }
        float inv = sInv[h];
        reinterpret_cast<float4*>(sO)[h * 8 + dq] =
            make_float4(acc.x * inv, acc.y * inv, acc.z * inv, acc.w * inv);
    }
    __syncthreads();
    {
        int cq = t & 63, kk = t >> 6;
        const float4* wo4 = reinterpret_cast<const float4*>(W_o);
        float4 acc = make_float4(0.f, 0.f, 0.f, 0.f);
        int kend = kk * 256 + 256;
#pragma unroll 4
        for (int k = kk * 256; k < kend; k++) {
            float s = sO[k];
            float4 w = wo4[(size_t)k * 64 + cq];
            acc.x += s * w.x;
            acc.y += s * w.y;
            acc.z += s * w.z;
            acc.w += s * w.w;
        }
        reinterpret_cast<float4*>(sPo)[kk * 64 + cq] = acc;
    }
    __syncthreads();
    {
        float v = sPo[t] + sPo[256 + t] + sPo[512 + t] + sPo[768 + t] + b_o[t];
        out[(size_t)n * 256 + t] = v;
    }

    // ---- phase 4b: out_dis ----
    {
        const float* dd = dis + ((size_t)b * LP * LQ + i) * 3;
        for (int idx = t; idx < 1536; idx += 256) {
            int j = idx / 3, d = idx - 3 * j;
            sDis[idx] = dd[(size_t)j * LQ * 3 + d];
        }
    }
    __syncthreads();
    if (t < 96) {
        int h = t & 31, d = t >> 5;
        float acc = 0.f;
#pragma unroll 4
        for (int j = 0; j < 512; j++) acc += sS[j * SST + 32 + h] * sDis[j * 3 + d];
        sOd[d * 32 + h] = acc * sInv[32 + h];
    }
    __syncthreads();
    if (t < 192) {
        int r3 = t >> 6, u = t & 63;
        float acc = b_d1[u];
#pragma unroll
        for (int k = 0; k < 32; k++) acc += sOd[r3 * 32 + k] * W_d1[k * 64 + u];
        sHd[r3 * 64 + u] = mishf(acc);
    }
    __syncthreads();
    if (t < 96) {
        int h = t & 31, d = t >> 5;
        float acc = b_d2[h];
#pragma unroll
        for (int k = 0; k < 64; k++) acc += sHd[d * 64 + k] * W_d2[k * 32 + h];
        out[524288 + ((size_t)n * 3 + d) * 32 + h] = acc;
    }
}

// ---------------- launch ----------------
extern "C" void kernel_launch(void* const* d_in, const int* in_sizes, int n_in,
                              void* d_out, int out_size) {
    const float* x = (const float*)d_in[0];
    const float* context = (const float*)d_in[1];
    const float* dis = (const float*)d_in[2];
    const float* dis_emb = (const float*)d_in[3];
    // scalars protein_len / ligand_len may or may not be materialized as inputs
    int wb = (n_in == 17) ? 4 : 6;
    const float* W_qk = (const float*)d_in[wb + 0];
    const float* W_cqk = (const float*)d_in[wb + 2];
    const float* W_cv = (const float*)d_in[wb + 3];
    const float* W_m1 = (const float*)d_in[wb + 4];
    const float* W_m2 = (const float*)d_in[wb + 5];
    const float* b_m2 = (const float*)d_in[wb + 6];
    const float* W_o = (const float*)d_in[wb + 7];
    const float* b_o = (const float*)d_in[wb + 8];
    const float* W_d1 = (const float*)d_in[wb + 9];
    const float* b_d1 = (const float*)d_in[wb + 10];
    const float* W_d2 = (const float*)d_in[wb + 11];
    const float* b_d2 = (const float*)d_in[wb + 12];
    float* out = (float*)d_out;

    // projections
    proj_gemm<<<dim3(32, 16), 256>>>(x, W_qk, 2048, 0);        // QK
    proj_gemm<<<dim3(128, 16), 256>>>(context, W_cqk, 8192, 1); // CQK (transposed)
    proj_gemm<<<dim3(128, 16), 256>>>(context, W_cv, 8192, 2);  // CV

    static int smem_set = 0;
    (void)smem_set;
    cudaFuncSetAttribute(fused_attn, cudaFuncAttributeMaxDynamicSharedMemorySize,
                         SMEM_BYTES);
    fused_attn<<<2048, 256, SMEM_BYTES>>>(dis, dis_emb, W_m1, W_m2, b_m2, W_o,
                                          b_o, W_d1, b_d1, W_d2, b_d2, out);
}

// round 4
// speedup vs baseline: 1.3008x; 1.2976x over previous
#include <cuda_runtime.h>
#include <math.h>

#define BATCH 16
#define LQ 128
#define LP 512
#define H 32
#define DH 32
#define SST 68                     /* padded row stride for s tile */
#define SCALE 0.17677669529663687f /* 32^-0.5 */

// ---------------- scratch (static device arrays; no allocs) ----------------
__device__ float g_QK[2048 * 1024];          // [n][h*32+d]
__device__ float g_CQKt[16 * 1024 * 512];    // [b][c=h*32+d][j]  (transposed)
__device__ float g_CV[8192 * 1024];          // [b*512+j][h*32+d]

// fast mish: x * (t^2-1)/(t^2+1), t = 1+e^x  (== x*tanh(softplus(x)))
__device__ __forceinline__ float mishf(float x) {
    if (x > 20.f) return x;
    float t = 1.f + __expf(x);
    float t2 = t * t;
    return x * __fdividef(t2 - 1.f, t2 + 1.f);
}

// ---------------- projection GEMM: out = A[M,256] @ W[256,1024] -----------
// mode 0 -> g_QK (plain), 1 -> g_CQKt (transposed per batch of 512 rows), 2 -> g_CV
__global__ __launch_bounds__(256) void proj_gemm(const float* __restrict__ A,
                                                 const float* __restrict__ W,
                                                 int M, int mode) {
    __shared__ float sAT[32][68];
    __shared__ float sB[32][68];
    __shared__ float sC[64][68];

    float* outp = (mode == 0) ? g_QK : (mode == 1 ? g_CQKt : g_CV);

    int t = threadIdx.x;
    int m0 = blockIdx.x * 64;
    int n0 = blockIdx.y * 64;
    int ty = t >> 4, tx = t & 15;

    float acc[4][4];
#pragma unroll
    for (int a = 0; a < 4; a++)
#pragma unroll
        for (int bq = 0; bq < 4; bq++) acc[a][bq] = 0.f;

    for (int k0 = 0; k0 < 256; k0 += 32) {
#pragma unroll
        for (int f = 0; f < 2; f++) {
            int qid = t + 256 * f;
            int r = qid >> 3, kq = qid & 7;
            float4 v = reinterpret_cast<const float4*>(A)[(size_t)(m0 + r) * 64 + (k0 >> 2) + kq];
            sAT[kq * 4 + 0][r] = v.x;
            sAT[kq * 4 + 1][r] = v.y;
            sAT[kq * 4 + 2][r] = v.z;
            sAT[kq * 4 + 3][r] = v.w;
        }
#pragma unroll
        for (int f = 0; f < 2; f++) {
            int qid = t + 256 * f;
            int kk = qid >> 4, cq = qid & 15;
            *reinterpret_cast<float4*>(&sB[kk][cq * 4]) =
                reinterpret_cast<const float4*>(W)[(size_t)(k0 + kk) * 256 + (n0 >> 2) + cq];
        }
        __syncthreads();
#pragma unroll
        for (int kk = 0; kk < 32; kk++) {
            float4 a4 = *reinterpret_cast<const float4*>(&sAT[kk][ty * 4]);
            float4 b4 = *reinterpret_cast<const float4*>(&sB[kk][tx * 4]);
            float av[4] = {a4.x, a4.y, a4.z, a4.w};
            float bv[4] = {b4.x, b4.y, b4.z, b4.w};
#pragma unroll
            for (int a = 0; a < 4; a++)
#pragma unroll
                for (int bq = 0; bq < 4; bq++) acc[a][bq] += av[a] * bv[bq];
        }
        __syncthreads();
    }

    if (mode != 1) {
#pragma unroll
        for (int a = 0; a < 4; a++) {
            float4 v = make_float4(acc[a][0], acc[a][1], acc[a][2], acc[a][3]);
            *reinterpret_cast<float4*>(&outp[(size_t)(m0 + ty * 4 + a) * 1024 + n0 + tx * 4]) = v;
        }
    } else {
#pragma unroll
        for (int a = 0; a < 4; a++) {
            float4 v = make_float4(acc[a][0], acc[a][1], acc[a][2], acc[a][3]);
            *reinterpret_cast<float4*>(&sC[ty * 4 + a][tx * 4]) = v;
        }
        __syncthreads();
        int bb = m0 >> 9;
        int jbase = m0 & 511;
#pragma unroll
        for (int f = 0; f < 16; f++) {
            int idx = t + 256 * f;
            int cc = idx >> 6, jj = idx & 63;
            outp[((size_t)bb * 1024 + n0 + cc) * 512 + jbase + jj] = sC[jj][cc];
        }
    }
}

// ---------------- fused attention kernel: one CTA per (b, i), 512 thr -----
// smem layout (float offsets):
#define OFF_S 0          /* 512*68 = 34816 */
#define OFF_QK 34816     /* 1024 */
#define OFF_H 35840      /* 8*128 = 1024 */
#define OFF_P 36864      /* 2048 (MLP partials; reused for AV + Wo partials) */
#define OFF_RED 38912    /* 8*64 = 512 */
#define OFF_MAX 39424    /* 64 */
#define OFF_INV 39488    /* 64 */
#define OFF_O 39552      /* 1024 */
#define OFF_DIS 40576    /* 1536 */
#define OFF_OD 42112     /* 96 */
#define OFF_HD 42208     /* 192 */
#define SMEM_FLOATS 42400
#define SMEM_BYTES (SMEM_FLOATS * 4)

__global__ __launch_bounds__(512, 1) void fused_attn(
    const float* __restrict__ dis, const float* __restrict__ dis_emb,
    const float* __restrict__ W_m1, const float* __restrict__ W_m2,
    const float* __restrict__ b_m2, const float* __restrict__ W_o,
    const float* __restrict__ b_o, const float* __restrict__ W_d1,
    const float* __restrict__ b_d1, const float* __restrict__ W_d2,
    const float* __restrict__ b_d2, float* __restrict__ out) {
    extern __shared__ float sm[];
    float* sS = sm + OFF_S;
    float* sQK = sm + OFF_QK;
    float* sH = sm + OFF_H;
    float* sP = sm + OFF_P;
    float* sRed = sm + OFF_RED;
    float* sMax = sm + OFF_MAX;
    float* sInv = sm + OFF_INV;
    float* sO = sm + OFF_O;
    float* sDis = sm + OFF_DIS;
    float* sOd = sm + OFF_OD;
    float* sHd = sm + OFF_HD;

    int t = threadIdx.x;
    int n = blockIdx.x;
    int b = n >> 7, i = n & 127;

    // ---- phase 0: load qk row + dis_emb channels ----
    reinterpret_cast<float2*>(sQK)[t] =
        reinterpret_cast<const float2*>(g_QK + (size_t)n * 1024)[t];
    const float* de = dis_emb + ((size_t)b * LP * LQ + i) * H;
    for (int idx = t; idx < LP * H; idx += 512) {
        int j = idx >> 5, h = idx & 31;
        sS[j * SST + 32 + h] = de[(size_t)j * LQ * H + h];
    }
    __syncthreads();

    // ---- phase 1: sim (coalesced over j via transposed CQK) ----
    {
        int jq = t & 127;        // j quad
        int h0 = (t >> 7) * 8;   // 8 heads per quarter
        const float4* cq = reinterpret_cast<const float4*>(g_CQKt);
#pragma unroll
        for (int hh = 0; hh < 8; hh++) {
            int h = h0 + hh;
            const float* qrow = sQK + h * 32;
            size_t base = ((size_t)b * 1024 + h * 32) * 128 + jq;
            float4 acc = make_float4(0.f, 0.f, 0.f, 0.f);
#pragma unroll
            for (int d = 0; d < 32; d++) {
                float q = qrow[d];
                float4 c4 = cq[base + (size_t)d * 128];
                acc.x += q * c4.x;
                acc.y += q * c4.y;
                acc.z += q * c4.z;
                acc.w += q * c4.w;
            }
            int j0 = jq * 4;
            sS[(j0 + 0) * SST + h] = acc.x * SCALE;
            sS[(j0 + 1) * SST + h] = acc.y * SCALE;
            sS[(j0 + 2) * SST + h] = acc.z * SCALE;
            sS[(j0 + 3) * SST + h] = acc.w * SCALE;
        }
    }
    __syncthreads();

    // ---- phase 2: attention MLP, 8 j-rows per iteration ----
    float w1[64], w2[32];
    int uA = t & 127;        // hidden unit (phase A)
    int jjA = t >> 7;        // 0..3 base jj (phase A)
    int cB = t & 63;         // out channel (phase B/C)
    int chB = (t >> 6) & 3;  // k-chunk (phase B)
    int jgB = t >> 8;        // 0..1 j-group (phase B)
    {
#pragma unroll
        for (int k = 0; k < 64; k++) w1[k] = W_m1[k * 128 + uA];
#pragma unroll
        for (int k = 0; k < 32; k++) w2[k] = W_m2[(chB * 32 + k) * 64 + cB];
    }
    float bm2 = b_m2[cB];

    for (int r = 0; r < 64; r++) {
        int j0 = r * 8;
        // A: hidden = mish(s @ W1) for 8 rows
#pragma unroll
        for (int s2 = 0; s2 < 2; s2++) {
            int jj = jjA + 4 * s2;
            const float4* srow = reinterpret_cast<const float4*>(sS + (j0 + jj) * SST);
            float acc = 0.f;
#pragma unroll
            for (int k4 = 0; k4 < 16; k4++) {
                float4 sv = srow[k4];
                acc += sv.x * w1[k4 * 4 + 0] + sv.y * w1[k4 * 4 + 1] +
                       sv.z * w1[k4 * 4 + 2] + sv.w * w1[k4 * 4 + 3];
            }
            sH[jj * 128 + uA] = mishf(acc);
        }
        __syncthreads();
        // B: partial out = hidden @ W2 (k split over 4 chunks)
#pragma unroll
        for (int j2 = 0; j2 < 4; j2++) {
            int jj = jgB * 4 + j2;
            const float4* hrow = reinterpret_cast<const float4*>(sH + jj * 128 + chB * 32);
            float p = 0.f;
#pragma unroll
            for (int k4 = 0; k4 < 8; k4++) {
                float4 hv = hrow[k4];
                p += hv.x * w2[k4 * 4 + 0] + hv.y * w2[k4 * 4 + 1] +
                     hv.z * w2[k4 * 4 + 2] + hv.w * w2[k4 * 4 + 3];
            }
            sP[jj * 256 + chB * 64 + cB] = p;
        }
        __syncthreads();
        // C: reduce partials + bias -> back into sS
        {
            int jj = t >> 6, c2 = t & 63;
            float v = sP[jj * 256 + c2] + sP[jj * 256 + 64 + c2] +
                      sP[jj * 256 + 128 + c2] + sP[jj * 256 + 192 + c2] + bm2;
            sS[(j0 + jj) * SST + c2] = v;
        }
        __syncthreads();
    }

    // ---- phase 3: softmax over j, per channel (8 j-groups of 64) ----
    {
        int c = t & 63, q = t >> 6;
        int jb = q * 64;
        float m = -1e30f;
        for (int j = jb; j < jb + 64; j++) m = fmaxf(m, sS[j * SST + c]);
        sRed[q * 64 + c] = m;
        __syncthreads();
        if (t < 64) {
            float mx = sRed[t];
#pragma unroll
            for (int g = 1; g < 8; g++) mx = fmaxf(mx, sRed[g * 64 + t]);
            sMax[t] = mx;
        }
        __syncthreads();
        float mx = sMax[c];
        float ssum = 0.f;
        for (int j = jb; j < jb + 64; j++) {
            float e = __expf(sS[j * SST + c] - mx);
            sS[j * SST + c] = e;
            ssum += e;
        }
        sRed[q * 64 + c] = ssum;
        __syncthreads();
        if (t < 64) {
            float sum = sRed[t];
#pragma unroll
            for (int g = 1; g < 8; g++) sum += sRed[g * 64 + t];
            sInv[t] = 1.f / sum;
        }
        __syncthreads();
    }

    // ---- phase 4a: out = (attn[:, :32] @ CV) @ W_o + b_o ----
    {
        int dq = t & 7, h = (t >> 3) & 31, jh = t >> 8;
        const float4* cv4 = reinterpret_cast<const float4*>(g_CV);
        size_t base = (size_t)b * 131072 + h * 8 + dq;
        float4 acc = make_float4(0.f, 0.f, 0.f, 0.f);
        int je = jh * 256 + 256;
#pragma unroll 4
        for (int j = jh * 256; j < je; j++) {
            float a = sS[j * SST + h];
            float4 v = cv4[base + (size_t)j * 256];
            acc.x += a * v.x;
            acc.y += a * v.y;
            acc.z += a * v.z;
            acc.w += a * v.w;
        }
        reinterpret_cast<float4*>(sP)[jh * 256 + h * 8 + dq] = acc;
    }
    __syncthreads();
    if (t < 256) {
        int h2 = t >> 3;
        float4 a = reinterpret_cast<float4*>(sP)[t];
        float4 b4 = reinterpret_cast<float4*>(sP)[256 + t];
        float inv = sInv[h2];
        reinterpret_cast<float4*>(sO)[t] = make_float4(
            (a.x + b4.x) * inv, (a.y + b4.y) * inv, (a.z + b4.z) * inv, (a.w + b4.w) * inv);
    }
    __syncthreads();
    {
        int cq = t & 63, kk = t >> 6;  // 8 k-chunks of 128
        const float4* wo4 = reinterpret_cast<const float4*>(W_o);
        float4 acc = make_float4(0.f, 0.f, 0.f, 0.f);
        int kend = kk * 128 + 128;
#pragma unroll 4
        for (int k = kk * 128; k < kend; k++) {
            float s = sO[k];
            float4 w = wo4[(size_t)k * 64 + cq];
            acc.x += s * w.x;
            acc.y += s * w.y;
            acc.z += s * w.z;
            acc.w += s * w.w;
        }
        reinterpret_cast<float4*>(sP)[kk * 64 + cq] = acc;
    }
    __syncthreads();
    if (t < 256) {
        float v = b_o[t];
#pragma unroll
        for (int kk = 0; kk < 8; kk++) v += sP[kk * 256 + t];
        out[(size_t)n * 256 + t] = v;
    }

    // ---- phase 4b: out_dis ----
    {
        const float* dd = dis + ((size_t)b * LP * LQ + i) * 3;
        for (int idx = t; idx < 1536; idx += 512) {
            int j = idx / 3, d = idx - 3 * j;
            sDis[idx] = dd[(size_t)j * LQ * 3 + d];
        }
    }
    __syncthreads();
    if (t < 96) {
        int h = t & 31, d = t >> 5;
        float acc = 0.f;
#pragma unroll 4
        for (int j = 0; j < 512; j++) acc += sS[j * SST + 32 + h] * sDis[j * 3 + d];
        sOd[d * 32 + h] = acc * sInv[32 + h];
    }
    __syncthreads();
    if (t < 192) {
        int r3 = t >> 6, u = t & 63;
        float acc = b_d1[u];
#pragma unroll
        for (int k = 0; k < 32; k++) acc += sOd[r3 * 32 + k] * W_d1[k * 64 + u];
        sHd[r3 * 64 + u] = mishf(acc);
    }
    __syncthreads();
    if (t < 96) {
        int h = t & 31, d = t >> 5;
        float acc = b_d2[h];
#pragma unroll
        for (int k = 0; k < 64; k++) acc += sHd[d * 64 + k] * W_d2[k * 32 + h];
        out[524288 + ((size_t)n * 3 + d) * 32 + h] = acc;
    }
}

// ---------------- launch ----------------
extern "C" void kernel_launch(void* const* d_in, const int* in_sizes, int n_in,
                              void* d_out, int out_size) {
    const float* x = (const float*)d_in[0];
    const float* context = (const float*)d_in[1];
    const float* dis = (const float*)d_in[2];
    const float* dis_emb = (const float*)d_in[3];
    int wb = (n_in == 17) ? 4 : 6;
    const float* W_qk = (const float*)d_in[wb + 0];
    const float* W_cqk = (const float*)d_in[wb + 2];
    const float* W_cv = (const float*)d_in[wb + 3];
    const float* W_m1 = (const float*)d_in[wb + 4];
    const float* W_m2 = (const float*)d_in[wb + 5];
    const float* b_m2 = (const float*)d_in[wb + 6];
    const float* W_o = (const float*)d_in[wb + 7];
    const float* b_o = (const float*)d_in[wb + 8];
    const float* W_d1 = (const float*)d_in[wb + 9];
    const float* b_d1 = (const float*)d_in[wb + 10];
    const float* W_d2 = (const float*)d_in[wb + 11];
    const float* b_d2 = (const float*)d_in[wb + 12];
    float* out = (float*)d_out;

    proj_gemm<<<dim3(32, 16), 256>>>(x, W_qk, 2048, 0);
    proj_gemm<<<dim3(128, 16), 256>>>(context, W_cqk, 8192, 1);
    proj_gemm<<<dim3(128, 16), 256>>>(context, W_cv, 8192, 2);

    cudaFuncSetAttribute(fused_attn, cudaFuncAttributeMaxDynamicSharedMemorySize,
                         SMEM_BYTES);
    fused_attn<<<2048, 512, SMEM_BYTES>>>(dis, dis_emb, W_m1, W_m2, b_m2, W_o,
                                          b_o, W_d1, b_d1, W_d2, b_d2, out);
}

// round 5
// speedup vs baseline: 2.4022x; 1.8468x over previous
#include <cuda_runtime.h>
#include <math.h>
#include <stdint.h>

#define BATCH 16
#define LQ 128
#define LP 512
#define H 32
#define DH 32
#define SST 68                     /* padded row stride for s tile */
#define SCALE 0.17677669529663687f /* 32^-0.5 */

// ---------------- scratch (static device arrays; no allocs) ----------------
__device__ float g_QK[2048 * 1024];          // [n][h*32+d]
__device__ float g_CQKt[16 * 1024 * 512];    // [b][c=h*32+d][j]  (transposed)
__device__ float g_CV[8192 * 1024];          // [b*512+j][h*32+d]

// fast mish: x * (t^2-1)/(t^2+1), t = 1+e^x  (== x*tanh(softplus(x)))
__device__ __forceinline__ float mishf(float x) {
    if (x > 20.f) return x;
    float t = 1.f + __expf(x);
    float t2 = t * t;
    return x * __fdividef(t2 - 1.f, t2 + 1.f);
}

__device__ __forceinline__ uint32_t tf32_cvt(float x) {
    uint32_t r;
    asm("cvt.rna.tf32.f32 %0, %1;" : "=r"(r) : "f"(x));
    return r;
}

__device__ __forceinline__ void mma_tf32(float* d, uint32_t a0, uint32_t a1,
                                         uint32_t a2, uint32_t a3, uint32_t b0,
                                         uint32_t b1) {
    asm volatile(
        "mma.sync.aligned.m16n8k8.row.col.f32.tf32.tf32.f32 "
        "{%0,%1,%2,%3}, {%4,%5,%6,%7}, {%8,%9}, {%0,%1,%2,%3};\n"
        : "+f"(d[0]), "+f"(d[1]), "+f"(d[2]), "+f"(d[3])
        : "r"(a0), "r"(a1), "r"(a2), "r"(a3), "r"(b0), "r"(b1));
}

// ---------------- projection GEMM: out = A[M,256] @ W[256,1024] -----------
__global__ __launch_bounds__(256) void proj_gemm(const float* __restrict__ A,
                                                 const float* __restrict__ W,
                                                 int M, int mode) {
    __shared__ float sAT[32][68];
    __shared__ float sB[32][68];
    __shared__ float sC[64][68];

    float* outp = (mode == 0) ? g_QK : (mode == 1 ? g_CQKt : g_CV);

    int t = threadIdx.x;
    int m0 = blockIdx.x * 64;
    int n0 = blockIdx.y * 64;
    int ty = t >> 4, tx = t & 15;

    float acc[4][4];
#pragma unroll
    for (int a = 0; a < 4; a++)
#pragma unroll
        for (int bq = 0; bq < 4; bq++) acc[a][bq] = 0.f;

    for (int k0 = 0; k0 < 256; k0 += 32) {
#pragma unroll
        for (int f = 0; f < 2; f++) {
            int qid = t + 256 * f;
            int r = qid >> 3, kq = qid & 7;
            float4 v = reinterpret_cast<const float4*>(A)[(size_t)(m0 + r) * 64 + (k0 >> 2) + kq];
            sAT[kq * 4 + 0][r] = v.x;
            sAT[kq * 4 + 1][r] = v.y;
            sAT[kq * 4 + 2][r] = v.z;
            sAT[kq * 4 + 3][r] = v.w;
        }
#pragma unroll
        for (int f = 0; f < 2; f++) {
            int qid = t + 256 * f;
            int kk = qid >> 4, cq = qid & 15;
            *reinterpret_cast<float4*>(&sB[kk][cq * 4]) =
                reinterpret_cast<const float4*>(W)[(size_t)(k0 + kk) * 256 + (n0 >> 2) + cq];
        }
        __syncthreads();
#pragma unroll
        for (int kk = 0; kk < 32; kk++) {
            float4 a4 = *reinterpret_cast<const float4*>(&sAT[kk][ty * 4]);
            float4 b4 = *reinterpret_cast<const float4*>(&sB[kk][tx * 4]);
            float av[4] = {a4.x, a4.y, a4.z, a4.w};
            float bv[4] = {b4.x, b4.y, b4.z, b4.w};
#pragma unroll
            for (int a = 0; a < 4; a++)
#pragma unroll
                for (int bq = 0; bq < 4; bq++) acc[a][bq] += av[a] * bv[bq];
        }
        __syncthreads();
    }

    if (mode != 1) {
#pragma unroll
        for (int a = 0; a < 4; a++) {
            float4 v = make_float4(acc[a][0], acc[a][1], acc[a][2], acc[a][3]);
            *reinterpret_cast<float4*>(&outp[(size_t)(m0 + ty * 4 + a) * 1024 + n0 + tx * 4]) = v;
        }
    } else {
#pragma unroll
        for (int a = 0; a < 4; a++) {
            float4 v = make_float4(acc[a][0], acc[a][1], acc[a][2], acc[a][3]);
            *reinterpret_cast<float4*>(&sC[ty * 4 + a][tx * 4]) = v;
        }
        __syncthreads();
        int bb = m0 >> 9;
        int jbase = m0 & 511;
#pragma unroll
        for (int f = 0; f < 16; f++) {
            int idx = t + 256 * f;
            int cc = idx >> 6, jj = idx & 63;
            outp[((size_t)bb * 1024 + n0 + cc) * 512 + jbase + jj] = sC[jj][cc];
        }
    }
}

// ---------------- fused attention kernel: one CTA per (b, i), 512 thr -----
// smem layout (float offsets):
#define OFF_S 0          /* 512*68 = 34816 */
#define OFF_QK 34816     /* 1024 */
#define OFF_P 35840      /* 2048 (AV + Wo partials) */
#define OFF_RED 37888    /* 512 */
#define OFF_MAX 38400    /* 64 */
#define OFF_INV 38464    /* 64 */
#define OFF_O 38528      /* 1024 */
#define OFF_DIS 39552    /* 1536 */
#define OFF_OD 41088     /* 96 */
#define OFF_HD 41184     /* 192 */
#define OFF_W1F 41376    /* 8192 : W1 fragment-ordered (float2 per lane) */
#define OFF_W2F 49568    /* 8192 : W2 fragment-ordered */
#define OFF_BM2 57760    /* 64 */
#define OFF_STG OFF_O    /* 16 warps x 16 x 10 = 2560, aliases sO+sDis */
#define SMEM_FLOATS 57824
#define SMEM_BYTES (SMEM_FLOATS * 4)

__global__ __launch_bounds__(512, 1) void fused_attn(
    const float* __restrict__ dis, const float* __restrict__ dis_emb,
    const float* __restrict__ W_m1, const float* __restrict__ W_m2,
    const float* __restrict__ b_m2, const float* __restrict__ W_o,
    const float* __restrict__ b_o, const float* __restrict__ W_d1,
    const float* __restrict__ b_d1, const float* __restrict__ W_d2,
    const float* __restrict__ b_d2, float* __restrict__ out) {
    extern __shared__ float sm[];
    float* sS = sm + OFF_S;
    float* sQK = sm + OFF_QK;
    float* sP = sm + OFF_P;
    float* sRed = sm + OFF_RED;
    float* sMax = sm + OFF_MAX;
    float* sInv = sm + OFF_INV;
    float* sO = sm + OFF_O;
    float* sDis = sm + OFF_DIS;
    float* sOd = sm + OFF_OD;
    float* sHd = sm + OFF_HD;
    float2* w1f = reinterpret_cast<float2*>(sm + OFF_W1F);
    float2* w2f = reinterpret_cast<float2*>(sm + OFF_W2F);

    int t = threadIdx.x;
    int n = blockIdx.x;
    int b = n >> 7, i = n & 127;

    // ---- phase 0: load qk row + dis_emb channels + build weight frags ----
    reinterpret_cast<float2*>(sQK)[t] =
        reinterpret_cast<const float2*>(g_QK + (size_t)n * 1024)[t];
    const float* de = dis_emb + ((size_t)b * LP * LQ + i) * H;
    for (int idx = t; idx < LP * H; idx += 512) {
        int j = idx >> 5, h = idx & 31;
        sS[j * SST + 32 + h] = de[(size_t)j * LQ * H + h];
    }
    // weight fragments (tf32-pre-rounded). 128 frags x 32 lanes each matrix.
#pragma unroll
    for (int p = 0; p < 8; p++) {
        int idx = t + 512 * p;  // 0..4095
        int fi = idx >> 5, ln = idx & 31;
        int gg = ln >> 2, tt = ln & 3;
        {
            int k8 = fi >> 4, nt = fi & 15;  // W1 frag = [k8][nt]
            float b0 = W_m1[(k8 * 8 + tt) * 128 + nt * 8 + gg];
            float b1 = W_m1[(k8 * 8 + tt + 4) * 128 + nt * 8 + gg];
            w1f[idx] = make_float2(__uint_as_float(tf32_cvt(b0)),
                                   __uint_as_float(tf32_cvt(b1)));
        }
        {
            int kt = fi >> 3, n2 = fi & 7;  // W2 frag = [kt][n2]
            float c0 = W_m2[(kt * 8 + tt) * 64 + n2 * 8 + gg];
            float c1 = W_m2[(kt * 8 + tt + 4) * 64 + n2 * 8 + gg];
            w2f[idx] = make_float2(__uint_as_float(tf32_cvt(c0)),
                                   __uint_as_float(tf32_cvt(c1)));
        }
    }
    if (t < 64) sm[OFF_BM2 + t] = b_m2[t];
    __syncthreads();

    // ---- phase 1: sim (coalesced over j via transposed CQK) ----
    {
        int jq = t & 127;
        int h0 = (t >> 7) * 8;
        const float4* cq = reinterpret_cast<const float4*>(g_CQKt);
#pragma unroll
        for (int hh = 0; hh < 8; hh++) {
            int h = h0 + hh;
            const float* qrow = sQK + h * 32;
            size_t base = ((size_t)b * 1024 + h * 32) * 128 + jq;
            float4 acc = make_float4(0.f, 0.f, 0.f, 0.f);
#pragma unroll
            for (int d = 0; d < 32; d++) {
                float q = qrow[d];
                float4 c4 = cq[base + (size_t)d * 128];
                acc.x += q * c4.x;
                acc.y += q * c4.y;
                acc.z += q * c4.z;
                acc.w += q * c4.w;
            }
            int j0 = jq * 4;
            sS[(j0 + 0) * SST + h] = acc.x * SCALE;
            sS[(j0 + 1) * SST + h] = acc.y * SCALE;
            sS[(j0 + 2) * SST + h] = acc.z * SCALE;
            sS[(j0 + 3) * SST + h] = acc.w * SCALE;
        }
    }
    __syncthreads();

    // ---- phase 2: attention MLP via mma.sync tf32, 32 j-rows per warp ----
    {
        int lane = t & 31;
        int w = t >> 5;
        int g = lane >> 2;   // 0..7
        int tig = lane & 3;  // 0..3
        int j0w = w * 32;
        float* stg = sm + OFF_STG + w * 160;  // 16 rows x stride 10

#pragma unroll
        for (int mt = 0; mt < 2; mt++) {
            int jr = j0w + mt * 16;
            float oacc[8][4];
#pragma unroll
            for (int n2 = 0; n2 < 8; n2++)
#pragma unroll
                for (int q = 0; q < 4; q++) oacc[n2][q] = 0.f;

#pragma unroll
            for (int nc = 0; nc < 4; nc++) {
                float hacc[4][4];
#pragma unroll
                for (int nt = 0; nt < 4; nt++)
#pragma unroll
                    for (int q = 0; q < 4; q++) hacc[nt][q] = 0.f;

#pragma unroll
                for (int k8 = 0; k8 < 8; k8++) {
                    const float* sr = sS + (jr + g) * SST + k8 * 8 + tig;
                    const float* sr8 = sr + 8 * SST;
                    uint32_t a0 = tf32_cvt(sr[0]);
                    uint32_t a1 = tf32_cvt(sr8[0]);
                    uint32_t a2 = tf32_cvt(sr[4]);
                    uint32_t a3 = tf32_cvt(sr8[4]);
#pragma unroll
                    for (int nt = 0; nt < 4; nt++) {
                        float2 bb = w1f[(k8 * 16 + nc * 4 + nt) * 32 + lane];
                        mma_tf32(hacc[nt], a0, a1, a2, a3,
                                 __float_as_uint(bb.x), __float_as_uint(bb.y));
                    }
                }
                // mish -> remap (per n8 tile = one k8 tile of GEMM2) -> GEMM2
#pragma unroll
                for (int nt = 0; nt < 4; nt++) {
                    int kt = nc * 4 + nt;
                    float m0 = mishf(hacc[nt][0]);
                    float m1 = mishf(hacc[nt][1]);
                    float m2 = mishf(hacc[nt][2]);
                    float m3 = mishf(hacc[nt][3]);
                    __syncwarp();
                    *reinterpret_cast<float2*>(&stg[g * 10 + 2 * tig]) =
                        make_float2(m0, m1);
                    *reinterpret_cast<float2*>(&stg[(g + 8) * 10 + 2 * tig]) =
                        make_float2(m2, m3);
                    __syncwarp();
                    uint32_t a0 = tf32_cvt(stg[g * 10 + tig]);
                    uint32_t a1 = tf32_cvt(stg[(g + 8) * 10 + tig]);
                    uint32_t a2 = tf32_cvt(stg[g * 10 + tig + 4]);
                    uint32_t a3 = tf32_cvt(stg[(g + 8) * 10 + tig + 4]);
#pragma unroll
                    for (int n2 = 0; n2 < 8; n2++) {
                        float2 bb = w2f[(kt * 8 + n2) * 32 + lane];
                        mma_tf32(oacc[n2], a0, a1, a2, a3,
                                 __float_as_uint(bb.x), __float_as_uint(bb.y));
                    }
                }
            }
            // write back MLP output (+bias) over the s tile rows
#pragma unroll
            for (int n2 = 0; n2 < 8; n2++) {
                int c0 = n2 * 8 + 2 * tig;
                float2 bia = *reinterpret_cast<const float2*>(&sm[OFF_BM2 + c0]);
                *reinterpret_cast<float2*>(&sS[(jr + g) * SST + c0]) =
                    make_float2(oacc[n2][0] + bia.x, oacc[n2][1] + bia.y);
                *reinterpret_cast<float2*>(&sS[(jr + g + 8) * SST + c0]) =
                    make_float2(oacc[n2][2] + bia.x, oacc[n2][3] + bia.y);
            }
        }
    }
    __syncthreads();

    // ---- phase 3: softmax over j, per channel (8 j-groups of 64) ----
    {
        int c = t & 63, q = t >> 6;
        int jb = q * 64;
        float m = -1e30f;
        for (int j = jb; j < jb + 64; j++) m = fmaxf(m, sS[j * SST + c]);
        sRed[q * 64 + c] = m;
        __syncthreads();
        if (t < 64) {
            float mx = sRed[t];
#pragma unroll
            for (int g = 1; g < 8; g++) mx = fmaxf(mx, sRed[g * 64 + t]);
            sMax[t] = mx;
        }
        __syncthreads();
        float mx = sMax[c];
        float ssum = 0.f;
        for (int j = jb; j < jb + 64; j++) {
            float e = __expf(sS[j * SST + c] - mx);
            sS[j * SST + c] = e;
            ssum += e;
        }
        sRed[q * 64 + c] = ssum;
        __syncthreads();
        if (t < 64) {
            float sum = sRed[t];
#pragma unroll
            for (int g = 1; g < 8; g++) sum += sRed[g * 64 + t];
            sInv[t] = 1.f / sum;
        }
        __syncthreads();
    }

    // ---- phase 4a: out = (attn[:, :32] @ CV) @ W_o + b_o ----
    {
        int dq = t & 7, h = (t >> 3) & 31, jh = t >> 8;
        const float4* cv4 = reinterpret_cast<const float4*>(g_CV);
        size_t base = (size_t)b * 131072 + h * 8 + dq;
        float4 acc = make_float4(0.f, 0.f, 0.f, 0.f);
        int je = jh * 256 + 256;
#pragma unroll 4
        for (int j = jh * 256; j < je; j++) {
            float a = sS[j * SST + h];
            float4 v = cv4[base + (size_t)j * 256];
            acc.x += a * v.x;
            acc.y += a * v.y;
            acc.z += a * v.z;
            acc.w += a * v.w;
        }
        reinterpret_cast<float4*>(sP)[jh * 256 + h * 8 + dq] = acc;
    }
    __syncthreads();
    if (t < 256) {
        int h2 = t >> 3;
        float4 a = reinterpret_cast<float4*>(sP)[t];
        float4 b4 = reinterpret_cast<float4*>(sP)[256 + t];
        float inv = sInv[h2];
        reinterpret_cast<float4*>(sO)[t] = make_float4(
            (a.x + b4.x) * inv, (a.y + b4.y) * inv, (a.z + b4.z) * inv, (a.w + b4.w) * inv);
    }
    __syncthreads();
    {
        int cq = t & 63, kk = t >> 6;
        const float4* wo4 = reinterpret_cast<const float4*>(W_o);
        float4 acc = make_float4(0.f, 0.f, 0.f, 0.f);
        int kend = kk * 128 + 128;
#pragma unroll 4
        for (int k = kk * 128; k < kend; k++) {
            float s = sO[k];
            float4 w = wo4[(size_t)k * 64 + cq];
            acc.x += s * w.x;
            acc.y += s * w.y;
            acc.z += s * w.z;
            acc.w += s * w.w;
        }
        reinterpret_cast<float4*>(sP)[kk * 64 + cq] = acc;
    }
    __syncthreads();
    if (t < 256) {
        float v = b_o[t];
#pragma unroll
        for (int kk = 0; kk < 8; kk++) v += sP[kk * 256 + t];
        out[(size_t)n * 256 + t] = v;
    }

    // ---- phase 4b: out_dis ----
    {
        const float* dd = dis + ((size_t)b * LP * LQ + i) * 3;
        for (int idx = t; idx < 1536; idx += 512) {
            int j = idx / 3, d = idx - 3 * j;
            sDis[idx] = dd[(size_t)j * LQ * 3 + d];
        }
    }
    __syncthreads();
    if (t < 96) {
        int h = t & 31, d = t >> 5;
        float acc = 0.f;
#pragma unroll 4
        for (int j = 0; j < 512; j++) acc += sS[j * SST + 32 + h] * sDis[j * 3 + d];
        sOd[d * 32 + h] = acc * sInv[32 + h];
    }
    __syncthreads();
    if (t < 192) {
        int r3 = t >> 6, u = t & 63;
        float acc = b_d1[u];
#pragma unroll
        for (int k = 0; k < 32; k++) acc += sOd[r3 * 32 + k] * W_d1[k * 64 + u];
        sHd[r3 * 64 + u] = mishf(acc);
    }
    __syncthreads();
    if (t < 96) {
        int h = t & 31, d = t >> 5;
        float acc = b_d2[h];
#pragma unroll
        for (int k = 0; k < 64; k++) acc += sHd[d * 64 + k] * W_d2[k * 32 + h];
        out[524288 + ((size_t)n * 3 + d) * 32 + h] = acc;
    }
}

// ---------------- launch ----------------
extern "C" void kernel_launch(void* const* d_in, const int* in_sizes, int n_in,
                              void* d_out, int out_size) {
    const float* x = (const float*)d_in[0];
    const float* context = (const float*)d_in[1];
    const float* dis = (const float*)d_in[2];
    const float* dis_emb = (const float*)d_in[3];
    int wb = (n_in == 17) ? 4 : 6;
    const float* W_qk = (const float*)d_in[wb + 0];
    const float* W_cqk = (const float*)d_in[wb + 2];
    const float* W_cv = (const float*)d_in[wb + 3];
    const float* W_m1 = (const float*)d_in[wb + 4];
    const float* W_m2 = (const float*)d_in[wb + 5];
    const float* b_m2 = (const float*)d_in[wb + 6];
    const float* W_o = (const float*)d_in[wb + 7];
    const float* b_o = (const float*)d_in[wb + 8];
    const float* W_d1 = (const float*)d_in[wb + 9];
    const float* b_d1 = (const float*)d_in[wb + 10];
    const float* W_d2 = (const float*)d_in[wb + 11];
    const float* b_d2 = (const float*)d_in[wb + 12];
    float* out = (float*)d_out;

    proj_gemm<<<dim3(32, 16), 256>>>(x, W_qk, 2048, 0);
    proj_gemm<<<dim3(128, 16), 256>>>(context, W_cqk, 8192, 1);
    proj_gemm<<<dim3(128, 16), 256>>>(context, W_cv, 8192, 2);

    cudaFuncSetAttribute(fused_attn, cudaFuncAttributeMaxDynamicSharedMemorySize,
                         SMEM_BYTES);
    fused_attn<<<2048, 512, SMEM_BYTES>>>(dis, dis_emb, W_m1, W_m2, b_m2, W_o,
                                          b_o, W_d1, b_d1, W_d2, b_d2, out);
}